// round 5
// baseline (speedup 1.0000x reference)
#include <cuda_runtime.h>
#include <cuda_bf16.h>
#include <cstdint>

// CompressionLayer grouped GEMM via mma.sync bf16 (HMMA), split-fused k-loop.
// y[b,n,o] = relu( sum_k x[b,n,k] * Wk[n,o,k] + bk[n,o] )
// Block = (btile of 32 batches, chunk n). D[32,64] = X[32,256] * W[64,256]^T
// 3-split bf16 (xh*wh + xh*wl + xl*wh, fp32 accum) with all splits fused per
// k-step: fragments loaded once via ldmatrix.x4, 6 MMAs per kstep per warp.

#define NTHREADS 256
#define BT 32

// smem byte offsets (rows are 512B = 256 bf16, XOR-quad swizzled)
#define S_XH   0        // 32 x 512  = 16384
#define S_XL   16384
#define S_WH   32768    // 64 x 512  = 32768
#define S_WL   65536
#define S_BIAS 98304    // 64 f32
#define S_TOTAL 98688

static __device__ __forceinline__ uint32_t smem_u32(const void* p) {
    uint32_t a;
    asm("{ .reg .u64 t; cvta.to.shared.u64 t, %1; cvt.u32.u64 %0, t; }"
        : "=r"(a) : "l"(p));
    return a;
}

static __device__ __forceinline__ void ldmatrix_x4(uint32_t& a0, uint32_t& a1,
                                                   uint32_t& a2, uint32_t& a3,
                                                   uint32_t addr) {
    asm volatile("ldmatrix.sync.aligned.m8n8.x4.shared.b16 {%0,%1,%2,%3}, [%4];"
                 : "=r"(a0), "=r"(a1), "=r"(a2), "=r"(a3) : "r"(addr));
}

static __device__ __forceinline__ void mma16816(float* c, uint32_t a0, uint32_t a1,
                                                uint32_t a2, uint32_t a3,
                                                uint32_t b0, uint32_t b1) {
    asm volatile(
        "mma.sync.aligned.m16n8k16.row.col.f32.bf16.bf16.f32 "
        "{%0,%1,%2,%3}, {%4,%5,%6,%7}, {%8,%9}, {%0,%1,%2,%3};"
        : "+f"(c[0]), "+f"(c[1]), "+f"(c[2]), "+f"(c[3])
        : "r"(a0), "r"(a1), "r"(a2), "r"(a3), "r"(b0), "r"(b1));
}

// split f32x4 into bf16 hi/lo and store 8B each into swizzled smem row
static __device__ __forceinline__ void cvt_store(char* sm, int off_hi, int off_lo,
                                                 int row, int k, float4 v) {
    __nv_bfloat162 h01 = __floats2bfloat162_rn(v.x, v.y);
    __nv_bfloat162 h23 = __floats2bfloat162_rn(v.z, v.w);
    float lx = v.x - __bfloat162float(h01.x);
    float ly = v.y - __bfloat162float(h01.y);
    float lz = v.z - __bfloat162float(h23.x);
    float lw = v.w - __bfloat162float(h23.y);
    __nv_bfloat162 l01 = __floats2bfloat162_rn(lx, ly);
    __nv_bfloat162 l23 = __floats2bfloat162_rn(lz, lw);
    int col  = k * 2;                                // byte col, multiple of 8
    int phys = row * 512 + (col ^ ((row & 7) << 4)); // quad-XOR swizzle
    *reinterpret_cast<uint2*>(sm + off_hi + phys) =
        make_uint2(*(uint32_t*)&h01, *(uint32_t*)&h23);
    *reinterpret_cast<uint2*>(sm + off_lo + phys) =
        make_uint2(*(uint32_t*)&l01, *(uint32_t*)&l23);
}

__global__ void __launch_bounds__(NTHREADS, 2)
compression_mma_kernel(const float* __restrict__ xg,
                       const float* __restrict__ Wg,
                       const float* __restrict__ bkg,
                       float* __restrict__ out) {
    extern __shared__ char sm[];
    const uint32_t sb = smem_u32(sm);
    const int tid = threadIdx.x;

    const int btile = blockIdx.x;      // 0..7   (fastest -> W[n] shared in-wave)
    const int n     = blockIdx.y;      // 0..1023
    const int ch    = n >> 5;
    const int cw    = n & 31;

    // ---- W[n]: 64x256 f32 -> bf16 hi/lo (16 float4 per thread) ----
    {
        const float4* Wg4 = reinterpret_cast<const float4*>(Wg + (size_t)n * 64 * 256);
        #pragma unroll
        for (int it = 0; it < 16; ++it) {
            int e  = tid + it * NTHREADS;   // 0..4095
            int o  = e >> 6;
            int k4 = (e & 63) << 2;
            cvt_store(sm, S_WH, S_WL, o, k4, Wg4[e]);
        }
    }
    if (tid < 64)
        reinterpret_cast<float*>(sm + S_BIAS)[tid] = bkg[n * 64 + tid];

    // ---- X tile: 32 batches x 256 k, chunk gather (8 float4/thread) ----
    {
        const float* xbase = xg + (size_t)(ch * 16) * 512 + cw * 16;
        #pragma unroll
        for (int it = 0; it < 8; ++it) {
            int e  = tid + it * NTHREADS;   // 0..2047
            int b  = e >> 6;
            int r  = e & 63;
            int i  = r >> 2;
            int j4 = (r & 3) << 2;
            int bglob = btile * BT + b;
            float4 v = *reinterpret_cast<const float4*>(
                xbase + (size_t)bglob * 262144 + i * 512 + j4);
            cvt_store(sm, S_XH, S_XL, b, i * 16 + j4, v);
        }
    }
    __syncthreads();

    // ---- compute: 8 warps, warp tile m16 x n16, splits fused per kstep ----
    const int wid = tid >> 5;
    const int lid = tid & 31;
    const int wm  = (wid & 1) << 4;     // 0 / 16
    const int wn  = (wid >> 1) << 4;    // 0 / 16 / 32 / 48

    // A ldmatrix lane address: rows m0-15 (lanes 0-15 k-lo 16B, 16-31 k-hi)
    const int arow = wm + (lid & 15);
    const uint32_t a_base = sb + arow * 512;
    const uint32_t a_sw   = (uint32_t)(arow & 7) << 4;
    const uint32_t a_coff = (uint32_t)(lid >> 4) << 4;  // 0 / 16

    // B ldmatrix lane address: lanes 0-7 n0-7@klo, 8-15 n0-7@khi,
    //                          16-23 n8-15@klo, 24-31 n8-15@khi
    const int bn = wn + ((lid >> 4) << 3) + (lid & 7);
    const uint32_t b_base = sb + bn * 512;
    const uint32_t b_sw   = (uint32_t)(bn & 7) << 4;
    const uint32_t b_coff = (uint32_t)((lid >> 3) & 1) << 4;  // 0 / 16

    float acc[2][4] = {{0.f, 0.f, 0.f, 0.f}, {0.f, 0.f, 0.f, 0.f}};

    #pragma unroll
    for (int s = 0; s < 16; ++s) {
        const uint32_t colA = ((uint32_t)s << 5) | a_coff;
        const uint32_t adr_a = a_base + (colA ^ a_sw);
        uint32_t xh0, xh1, xh2, xh3, xl0, xl1, xl2, xl3;
        ldmatrix_x4(xh0, xh1, xh2, xh3, adr_a + S_XH);
        ldmatrix_x4(xl0, xl1, xl2, xl3, adr_a + S_XL);

        const uint32_t colB = ((uint32_t)s << 5) | b_coff;
        const uint32_t adr_b = b_base + (colB ^ b_sw);
        uint32_t wh0, wh1, wh2, wh3, wl0, wl1, wl2, wl3;
        ldmatrix_x4(wh0, wh1, wh2, wh3, adr_b + S_WH);
        ldmatrix_x4(wl0, wl1, wl2, wl3, adr_b + S_WL);

        // 6 MMAs: xh*wh, xh*wl, xl*wh for both n8 tiles (2 indep acc chains)
        mma16816(acc[0], xh0, xh1, xh2, xh3, wh0, wh1);
        mma16816(acc[1], xh0, xh1, xh2, xh3, wh2, wh3);
        mma16816(acc[0], xh0, xh1, xh2, xh3, wl0, wl1);
        mma16816(acc[1], xh0, xh1, xh2, xh3, wl2, wl3);
        mma16816(acc[0], xl0, xl1, xl2, xl3, wh0, wh1);
        mma16816(acc[1], xl0, xl1, xl2, xl3, wh2, wh3);
    }

    // ---- epilogue: bias + relu, scatter ----
    const int g = lid >> 2;
    const int t = lid & 3;
    const float* Bs = reinterpret_cast<const float*>(sm + S_BIAS);
    #pragma unroll
    for (int nt = 0; nt < 2; ++nt) {
        int ob  = wn + nt * 8;          // multiple of 8
        int oi  = ob >> 3;
        int oj  = 2 * t;
        float bi0 = Bs[ob + oj];
        float bi1 = Bs[ob + oj + 1];

        size_t colofs = (size_t)(ch * 8 + oi) * 256 + cw * 8 + oj;
        int bg0 = btile * BT + wm + g;
        float2 v0 = make_float2(fmaxf(acc[nt][0] + bi0, 0.f),
                                fmaxf(acc[nt][1] + bi1, 0.f));
        *reinterpret_cast<float2*>(out + (size_t)bg0 * 65536 + colofs) = v0;

        int bg1 = bg0 + 8;
        float2 v1 = make_float2(fmaxf(acc[nt][2] + bi0, 0.f),
                                fmaxf(acc[nt][3] + bi1, 0.f));
        *reinterpret_cast<float2*>(out + (size_t)bg1 * 65536 + colofs) = v1;
    }
}

extern "C" void kernel_launch(void* const* d_in, const int* in_sizes, int n_in,
                              void* d_out, int out_size) {
    const float* x  = (const float*)d_in[0];   // [256,512,512]
    const float* Wk = (const float*)d_in[1];   // [1024,64,256]
    const float* bk = (const float*)d_in[2];   // [1024,64]
    float* out = (float*)d_out;                // [256, 65536]

    cudaFuncSetAttribute(compression_mma_kernel,
                         cudaFuncAttributeMaxDynamicSharedMemorySize, S_TOTAL);

    dim3 grid(8, 1024);   // btile fastest: CTAs sharing W[n] adjacent in wave
    compression_mma_kernel<<<grid, NTHREADS, S_TOTAL>>>(x, Wk, bk, out);
}

// round 6
// speedup vs baseline: 2.3093x; 2.3093x over previous
#include <cuda_runtime.h>
#include <cuda_fp16.h>
#include <cstdint>

// CompressionLayer grouped GEMM via mma.sync fp16 (f32 accumulate).
// y[b,n,o] = relu( sum_k x[b,n,k] * Wk[n,o,k] + bk[n,o] )
// Single fp16 MMA (no split): input rounding 2^-12 rms, incoherent over K=256
// -> norm rel_err ~3e-4 < 1e-3 threshold. fp32 accum via HMMA.
// Block = (btile of 64 batches, chunk n). D[64,64] = X[64,256] * W[64,256]^T
// smem 64.3KB -> 3 CTAs/SM. grid(4,1024): CTAs sharing W[n] adjacent.

#define NTHREADS 256
#define BT 64

// smem byte offsets (rows are 512B = 256 fp16, XOR-quad swizzled)
#define S_X    0        // 64 x 512 = 32768
#define S_W    32768    // 64 x 512 = 32768
#define S_BIAS 65536    // 64 f32
#define S_TOTAL 65792

static __device__ __forceinline__ uint32_t smem_u32(const void* p) {
    uint32_t a;
    asm("{ .reg .u64 t; cvta.to.shared.u64 t, %1; cvt.u32.u64 %0, t; }"
        : "=r"(a) : "l"(p));
    return a;
}

static __device__ __forceinline__ void ldmatrix_x4(uint32_t& a0, uint32_t& a1,
                                                   uint32_t& a2, uint32_t& a3,
                                                   uint32_t addr) {
    asm volatile("ldmatrix.sync.aligned.m8n8.x4.shared.b16 {%0,%1,%2,%3}, [%4];"
                 : "=r"(a0), "=r"(a1), "=r"(a2), "=r"(a3) : "r"(addr));
}

static __device__ __forceinline__ void mma16816(float* c, uint32_t a0, uint32_t a1,
                                                uint32_t a2, uint32_t a3,
                                                uint32_t b0, uint32_t b1) {
    asm volatile(
        "mma.sync.aligned.m16n8k16.row.col.f32.f16.f16.f32 "
        "{%0,%1,%2,%3}, {%4,%5,%6,%7}, {%8,%9}, {%0,%1,%2,%3};"
        : "+f"(c[0]), "+f"(c[1]), "+f"(c[2]), "+f"(c[3])
        : "r"(a0), "r"(a1), "r"(a2), "r"(a3), "r"(b0), "r"(b1));
}

// f32x4 -> fp16x4, store 8B into swizzled smem row
static __device__ __forceinline__ void cvt_store(char* sm, int off,
                                                 int row, int k, float4 v) {
    __half2 h01 = __floats2half2_rn(v.x, v.y);
    __half2 h23 = __floats2half2_rn(v.z, v.w);
    int phys = row * 512 + ((k * 2) ^ ((row & 7) << 4));
    *reinterpret_cast<uint2*>(sm + off + phys) =
        make_uint2(*(uint32_t*)&h01, *(uint32_t*)&h23);
}

__global__ void __launch_bounds__(NTHREADS, 3)
compression_mma_kernel(const float* __restrict__ xg,
                       const float* __restrict__ Wg,
                       const float* __restrict__ bkg,
                       float* __restrict__ out) {
    extern __shared__ char sm[];
    const uint32_t sb = smem_u32(sm);
    const int tid = threadIdx.x;

    const int btile = blockIdx.x;      // 0..3   (fastest -> W[n] shared in-wave)
    const int n     = blockIdx.y;      // 0..1023
    const int ch    = n >> 5;
    const int cw    = n & 31;

    // ---- W[n]: 64x256 f32 -> fp16 (16 float4 per thread) ----
    {
        const float4* Wg4 = reinterpret_cast<const float4*>(Wg + (size_t)n * 64 * 256);
        #pragma unroll
        for (int it = 0; it < 16; ++it) {
            int e  = tid + it * NTHREADS;   // 0..4095
            int o  = e >> 6;
            int k4 = (e & 63) << 2;
            cvt_store(sm, S_W, o, k4, Wg4[e]);
        }
    }
    if (tid < 64)
        reinterpret_cast<float*>(sm + S_BIAS)[tid] = bkg[n * 64 + tid];

    // ---- X tile: 64 batches x 256 k, chunk gather (16 float4/thread) ----
    {
        const float* xbase = xg + (size_t)(ch * 16) * 512 + cw * 16;
        #pragma unroll
        for (int it = 0; it < 16; ++it) {
            int e  = tid + it * NTHREADS;   // 0..4095
            int b  = e >> 6;
            int r  = e & 63;
            int i  = r >> 2;
            int j4 = (r & 3) << 2;
            int bglob = btile * BT + b;
            float4 v = *reinterpret_cast<const float4*>(
                xbase + (size_t)bglob * 262144 + i * 512 + j4);
            cvt_store(sm, S_X, b, i * 16 + j4, v);
        }
    }
    __syncthreads();

    // ---- compute: 8 warps, warp tile m32 x n16 ----
    const int wid = tid >> 5;
    const int lid = tid & 31;
    const int wm  = (wid & 1) << 5;     // 0 / 32
    const int wn  = (wid >> 1) << 4;    // 0 / 16 / 32 / 48

    // A ldmatrix lane addresses for the two m16 sub-tiles
    const int ar0 = wm + (lid & 15);
    const int ar1 = ar0 + 16;
    const uint32_t a0_base = sb + S_X + ar0 * 512;
    const uint32_t a1_base = sb + S_X + ar1 * 512;
    const uint32_t a0_sw   = (uint32_t)(ar0 & 7) << 4;
    const uint32_t a1_sw   = (uint32_t)(ar1 & 7) << 4;
    const uint32_t a_coff  = (uint32_t)(lid >> 4) << 4;  // 0 / 16

    // B ldmatrix: lanes 0-7 n0-7@klo, 8-15 n0-7@khi, 16-23 n8-15@klo, 24-31 @khi
    const int bn = wn + ((lid >> 4) << 3) + (lid & 7);
    const uint32_t b_base = sb + S_W + bn * 512;
    const uint32_t b_sw   = (uint32_t)(bn & 7) << 4;
    const uint32_t b_coff = (uint32_t)((lid >> 3) & 1) << 4;  // 0 / 16

    float acc[2][2][4];
    #pragma unroll
    for (int i = 0; i < 2; ++i)
        #pragma unroll
        for (int j = 0; j < 2; ++j)
            #pragma unroll
            for (int e = 0; e < 4; ++e) acc[i][j][e] = 0.f;

    #pragma unroll
    for (int s = 0; s < 16; ++s) {
        const uint32_t colA = ((uint32_t)s << 5) | a_coff;
        uint32_t x00, x01, x02, x03, x10, x11, x12, x13;
        ldmatrix_x4(x00, x01, x02, x03, a0_base + (colA ^ a0_sw));
        ldmatrix_x4(x10, x11, x12, x13, a1_base + (colA ^ a1_sw));

        const uint32_t colB = ((uint32_t)s << 5) | b_coff;
        uint32_t w0, w1, w2, w3;
        ldmatrix_x4(w0, w1, w2, w3, b_base + (colB ^ b_sw));

        mma16816(acc[0][0], x00, x01, x02, x03, w0, w1);
        mma16816(acc[0][1], x00, x01, x02, x03, w2, w3);
        mma16816(acc[1][0], x10, x11, x12, x13, w0, w1);
        mma16816(acc[1][1], x10, x11, x12, x13, w2, w3);
    }

    // ---- epilogue: bias + relu, scatter ----
    const int g = lid >> 2;
    const int t = lid & 3;
    const float* Bs = reinterpret_cast<const float*>(sm + S_BIAS);
    #pragma unroll
    for (int mt = 0; mt < 2; ++mt) {
        #pragma unroll
        for (int nt = 0; nt < 2; ++nt) {
            int ob  = wn + nt * 8;          // multiple of 8
            int oi  = ob >> 3;
            int oj  = 2 * t;
            float bi0 = Bs[ob + oj];
            float bi1 = Bs[ob + oj + 1];

            size_t colofs = (size_t)(ch * 8 + oi) * 256 + cw * 8 + oj;
            int bg0 = btile * BT + wm + mt * 16 + g;
            float2 v0 = make_float2(fmaxf(acc[mt][nt][0] + bi0, 0.f),
                                    fmaxf(acc[mt][nt][1] + bi1, 0.f));
            *reinterpret_cast<float2*>(out + (size_t)bg0 * 65536 + colofs) = v0;

            int bg1 = bg0 + 8;
            float2 v1 = make_float2(fmaxf(acc[mt][nt][2] + bi0, 0.f),
                                    fmaxf(acc[mt][nt][3] + bi1, 0.f));
            *reinterpret_cast<float2*>(out + (size_t)bg1 * 65536 + colofs) = v1;
        }
    }
}

extern "C" void kernel_launch(void* const* d_in, const int* in_sizes, int n_in,
                              void* d_out, int out_size) {
    const float* x  = (const float*)d_in[0];   // [256,512,512]
    const float* Wk = (const float*)d_in[1];   // [1024,64,256]
    const float* bk = (const float*)d_in[2];   // [1024,64]
    float* out = (float*)d_out;                // [256, 65536]

    cudaFuncSetAttribute(compression_mma_kernel,
                         cudaFuncAttributeMaxDynamicSharedMemorySize, S_TOTAL);

    dim3 grid(4, 1024);   // btile fastest: CTAs sharing W[n] adjacent in wave
    compression_mma_kernel<<<grid, NTHREADS, S_TOTAL>>>(x, Wk, bk, out);
}

// round 7
// speedup vs baseline: 2.3625x; 1.0231x over previous
#include <cuda_runtime.h>
#include <cuda_fp16.h>
#include <cstdint>

// CompressionLayer grouped GEMM via mma.sync fp16 (f32 accumulate).
// y[b,n,o] = relu( sum_k x[b,n,k] * Wk[n,o,k] + bk[n,o] )
// Block = (btile of 128 batches, chunk n). D[128,64] = X[128,256]*W[64,256]^T
// Warp grid 4(m) x 2(n), warp tile m32 x n32 -> A repl 2, B repl 4:
// mainloop LDS 256KB/CTA for 2 work-units (was 192KB for 1).

#define NTHREADS 256
#define BT 128

// smem byte offsets (rows are 512B = 256 fp16, XOR-quad swizzled)
#define S_X    0        // 128 x 512 = 65536
#define S_W    65536    // 64 x 512  = 32768
#define S_BIAS 98304    // 64 f32
#define S_TOTAL 98560

static __device__ __forceinline__ uint32_t smem_u32(const void* p) {
    uint32_t a;
    asm("{ .reg .u64 t; cvta.to.shared.u64 t, %1; cvt.u32.u64 %0, t; }"
        : "=r"(a) : "l"(p));
    return a;
}

static __device__ __forceinline__ void ldmatrix_x4(uint32_t& a0, uint32_t& a1,
                                                   uint32_t& a2, uint32_t& a3,
                                                   uint32_t addr) {
    asm volatile("ldmatrix.sync.aligned.m8n8.x4.shared.b16 {%0,%1,%2,%3}, [%4];"
                 : "=r"(a0), "=r"(a1), "=r"(a2), "=r"(a3) : "r"(addr));
}

static __device__ __forceinline__ void mma16816(float* c, uint32_t a0, uint32_t a1,
                                                uint32_t a2, uint32_t a3,
                                                uint32_t b0, uint32_t b1) {
    asm volatile(
        "mma.sync.aligned.m16n8k16.row.col.f32.f16.f16.f32 "
        "{%0,%1,%2,%3}, {%4,%5,%6,%7}, {%8,%9}, {%0,%1,%2,%3};"
        : "+f"(c[0]), "+f"(c[1]), "+f"(c[2]), "+f"(c[3])
        : "r"(a0), "r"(a1), "r"(a2), "r"(a3), "r"(b0), "r"(b1));
}

// f32x4 -> fp16x4, store 8B into swizzled smem row
static __device__ __forceinline__ void cvt_store(char* sm, int off,
                                                 int row, int k, float4 v) {
    __half2 h01 = __floats2half2_rn(v.x, v.y);
    __half2 h23 = __floats2half2_rn(v.z, v.w);
    int phys = row * 512 + ((k * 2) ^ ((row & 7) << 4));
    *reinterpret_cast<uint2*>(sm + off + phys) =
        make_uint2(*(uint32_t*)&h01, *(uint32_t*)&h23);
}

__global__ void __launch_bounds__(NTHREADS, 2)
compression_mma_kernel(const float* __restrict__ xg,
                       const float* __restrict__ Wg,
                       const float* __restrict__ bkg,
                       float* __restrict__ out) {
    extern __shared__ char sm[];
    const uint32_t sb = smem_u32(sm);
    const int tid = threadIdx.x;

    const int btile = blockIdx.x;      // 0..1   (fastest -> W[n] shared in-wave)
    const int n     = blockIdx.y;      // 0..1023
    const int ch    = n >> 5;
    const int cw    = n & 31;

    // ---- W[n]: 64x256 f32 -> fp16 (16 float4 per thread) ----
    {
        const float4* Wg4 = reinterpret_cast<const float4*>(Wg + (size_t)n * 64 * 256);
        #pragma unroll
        for (int it = 0; it < 16; ++it) {
            int e  = tid + it * NTHREADS;   // 0..4095
            int o  = e >> 6;
            int k4 = (e & 63) << 2;
            cvt_store(sm, S_W, o, k4, Wg4[e]);
        }
    }
    if (tid < 64)
        reinterpret_cast<float*>(sm + S_BIAS)[tid] = bkg[n * 64 + tid];

    // ---- X tile: 128 batches x 256 k, chunk gather (32 float4/thread) ----
    {
        const float* xbase = xg + (size_t)(ch * 16) * 512 + cw * 16;
        #pragma unroll
        for (int it = 0; it < 32; ++it) {
            int e  = tid + it * NTHREADS;   // 0..8191
            int b  = e >> 6;
            int r  = e & 63;
            int i  = r >> 2;
            int j4 = (r & 3) << 2;
            int bglob = btile * BT + b;
            float4 v = *reinterpret_cast<const float4*>(
                xbase + (size_t)bglob * 262144 + i * 512 + j4);
            cvt_store(sm, S_X, b, i * 16 + j4, v);
        }
    }
    __syncthreads();

    // ---- compute: 8 warps as 4(m) x 2(n), warp tile m32 x n32 ----
    const int wid = tid >> 5;
    const int lid = tid & 31;
    const int wm  = (wid & 3) << 5;     // 0/32/64/96
    const int wn  = (wid >> 2) << 5;    // 0/32

    // A ldmatrix lane addresses for the two m16 sub-tiles
    const int ar0 = wm + (lid & 15);
    const int ar1 = ar0 + 16;
    const uint32_t a0_base = sb + S_X + ar0 * 512;
    const uint32_t a1_base = sb + S_X + ar1 * 512;
    const uint32_t a0_sw   = (uint32_t)(ar0 & 7) << 4;
    const uint32_t a1_sw   = (uint32_t)(ar1 & 7) << 4;
    const uint32_t a_coff  = (uint32_t)(lid >> 4) << 4;  // 0 / 16

    // B ldmatrix lane addresses for the two n16 sub-tiles
    const int bn0 = wn + ((lid >> 4) << 3) + (lid & 7);
    const int bn1 = bn0 + 16;
    const uint32_t b0_base = sb + S_W + bn0 * 512;
    const uint32_t b1_base = sb + S_W + bn1 * 512;
    const uint32_t b0_sw   = (uint32_t)(bn0 & 7) << 4;
    const uint32_t b1_sw   = (uint32_t)(bn1 & 7) << 4;
    const uint32_t b_coff  = (uint32_t)((lid >> 3) & 1) << 4;  // 0 / 16

    float acc[2][4][4];
    #pragma unroll
    for (int i = 0; i < 2; ++i)
        #pragma unroll
        for (int j = 0; j < 4; ++j)
            #pragma unroll
            for (int e = 0; e < 4; ++e) acc[i][j][e] = 0.f;

    #pragma unroll
    for (int s = 0; s < 16; ++s) {
        const uint32_t colA = ((uint32_t)s << 5) | a_coff;
        uint32_t x00, x01, x02, x03, x10, x11, x12, x13;
        ldmatrix_x4(x00, x01, x02, x03, a0_base + (colA ^ a0_sw));
        ldmatrix_x4(x10, x11, x12, x13, a1_base + (colA ^ a1_sw));

        const uint32_t colB = ((uint32_t)s << 5) | b_coff;
        uint32_t u0, u1, u2, u3, v0, v1, v2, v3;
        ldmatrix_x4(u0, u1, u2, u3, b0_base + (colB ^ b0_sw));
        ldmatrix_x4(v0, v1, v2, v3, b1_base + (colB ^ b1_sw));

        mma16816(acc[0][0], x00, x01, x02, x03, u0, u1);
        mma16816(acc[0][1], x00, x01, x02, x03, u2, u3);
        mma16816(acc[0][2], x00, x01, x02, x03, v0, v1);
        mma16816(acc[0][3], x00, x01, x02, x03, v2, v3);
        mma16816(acc[1][0], x10, x11, x12, x13, u0, u1);
        mma16816(acc[1][1], x10, x11, x12, x13, u2, u3);
        mma16816(acc[1][2], x10, x11, x12, x13, v0, v1);
        mma16816(acc[1][3], x10, x11, x12, x13, v2, v3);
    }

    // ---- epilogue: bias + relu, scatter ----
    const int g = lid >> 2;
    const int t = lid & 3;
    const float* Bs = reinterpret_cast<const float*>(sm + S_BIAS);
    #pragma unroll
    for (int mt = 0; mt < 2; ++mt) {
        #pragma unroll
        for (int nt = 0; nt < 4; ++nt) {
            int ob  = wn + nt * 8;          // multiple of 8
            int oi  = ob >> 3;
            int oj  = 2 * t;
            float bi0 = Bs[ob + oj];
            float bi1 = Bs[ob + oj + 1];

            size_t colofs = (size_t)(ch * 8 + oi) * 256 + cw * 8 + oj;
            int bg0 = btile * BT + wm + mt * 16 + g;
            float2 w0 = make_float2(fmaxf(acc[mt][nt][0] + bi0, 0.f),
                                    fmaxf(acc[mt][nt][1] + bi1, 0.f));
            *reinterpret_cast<float2*>(out + (size_t)bg0 * 65536 + colofs) = w0;

            int bg1 = bg0 + 8;
            float2 w1 = make_float2(fmaxf(acc[mt][nt][2] + bi0, 0.f),
                                    fmaxf(acc[mt][nt][3] + bi1, 0.f));
            *reinterpret_cast<float2*>(out + (size_t)bg1 * 65536 + colofs) = w1;
        }
    }
}

extern "C" void kernel_launch(void* const* d_in, const int* in_sizes, int n_in,
                              void* d_out, int out_size) {
    const float* x  = (const float*)d_in[0];   // [256,512,512]
    const float* Wk = (const float*)d_in[1];   // [1024,64,256]
    const float* bk = (const float*)d_in[2];   // [1024,64]
    float* out = (float*)d_out;                // [256, 65536]

    cudaFuncSetAttribute(compression_mma_kernel,
                         cudaFuncAttributeMaxDynamicSharedMemorySize, S_TOTAL);

    dim3 grid(2, 1024);   // btile fastest: CTAs sharing W[n] adjacent in wave
    compression_mma_kernel<<<grid, NTHREADS, S_TOTAL>>>(x, Wk, bk, out);
}

// round 8
// speedup vs baseline: 2.5237x; 1.0682x over previous
#include <cuda_runtime.h>
#include <cuda_fp16.h>
#include <cstdint>

// CompressionLayer grouped GEMM via mma.sync fp16 (f32 accumulate),
// k-staged software pipeline overlapping X loads with MMA compute.
// y[b,n,o] = relu( sum_k x[b,n,k] * Wk[n,o,k] + bk[n,o] )
// Block = (btile of 128 batches, chunk n). D[128,64] = X[128,256]*W[64,256]^T
// W loaded fully in prologue; X pipelined in 4 k-stages of 64 (double buffer).

#define NTHREADS 256
#define BT 128

// smem layout
#define S_W     0        // 64 rows x 512B (256 fp16), swizzled
#define S_X0    32768    // stage buf 0: 128 rows x 128B (64 fp16)
#define S_X1    49152    // stage buf 1
#define S_BIAS  65536    // 64 f32
#define S_TOTAL 65792

static __device__ __forceinline__ uint32_t smem_u32(const void* p) {
    uint32_t a;
    asm("{ .reg .u64 t; cvta.to.shared.u64 t, %1; cvt.u32.u64 %0, t; }"
        : "=r"(a) : "l"(p));
    return a;
}

static __device__ __forceinline__ void ldmatrix_x4(uint32_t& a0, uint32_t& a1,
                                                   uint32_t& a2, uint32_t& a3,
                                                   uint32_t addr) {
    asm volatile("ldmatrix.sync.aligned.m8n8.x4.shared.b16 {%0,%1,%2,%3}, [%4];"
                 : "=r"(a0), "=r"(a1), "=r"(a2), "=r"(a3) : "r"(addr));
}

static __device__ __forceinline__ void mma16816(float* c, uint32_t a0, uint32_t a1,
                                                uint32_t a2, uint32_t a3,
                                                uint32_t b0, uint32_t b1) {
    asm volatile(
        "mma.sync.aligned.m16n8k16.row.col.f32.f16.f16.f32 "
        "{%0,%1,%2,%3}, {%4,%5,%6,%7}, {%8,%9}, {%0,%1,%2,%3};"
        : "+f"(c[0]), "+f"(c[1]), "+f"(c[2]), "+f"(c[3])
        : "r"(a0), "r"(a1), "r"(a2), "r"(a3), "r"(b0), "r"(b1));
}

// f32x4 -> fp16x4, 8B store into swizzled row of given byte stride
template <int STRIDE>
static __device__ __forceinline__ void cvt_store(char* dst, int row, int kcol,
                                                 float4 v) {
    __half2 h01 = __floats2half2_rn(v.x, v.y);
    __half2 h23 = __floats2half2_rn(v.z, v.w);
    int phys = row * STRIDE + ((kcol * 2) ^ ((row & 7) << 4));
    *reinterpret_cast<uint2*>(dst + phys) =
        make_uint2(*(uint32_t*)&h01, *(uint32_t*)&h23);
}

__global__ void __launch_bounds__(NTHREADS, 2)
compression_mma_kernel(const float* __restrict__ xg,
                       const float* __restrict__ Wg,
                       const float* __restrict__ bkg,
                       float* __restrict__ out) {
    extern __shared__ char sm[];
    const uint32_t sb = smem_u32(sm);
    const int tid = threadIdx.x;

    const int btile = blockIdx.x;      // 0..1 (fastest -> W[n] shared in-wave)
    const int n     = blockIdx.y;      // 0..1023
    const int ch    = n >> 5;
    const int cw    = n & 31;

    // ---- prologue: W[n] 64x256 f32 -> fp16 smem (full), bias ----
    {
        const float4* Wg4 = reinterpret_cast<const float4*>(Wg + (size_t)n * 64 * 256);
        #pragma unroll
        for (int it = 0; it < 16; ++it) {
            int e  = tid + it * NTHREADS;   // 0..4095
            int o  = e >> 6;
            int k4 = (e & 63) << 2;
            cvt_store<512>(sm + S_W, o, k4, Wg4[e]);
        }
    }
    if (tid < 64)
        reinterpret_cast<float*>(sm + S_BIAS)[tid] = bkg[n * 64 + tid];

    // ---- X stage loader: stage covers k in [64*stage, 64*stage+64) ----
    const float* xbase = xg + (size_t)(ch * 16) * 512 + cw * 16
                            + (size_t)(btile * BT) * 262144;
    const int b_  = tid >> 1;                 // 0..127 (2 threads per batch)
    const int h_  = tid & 1;                  // half-row pair selector

    // per stage: each thread loads 8 float4 (its batch, rows 4s..4s+3, 2 j4s)
    #define X_LDG(regs, stage)                                                \
        {                                                                     \
            const float* p = xbase + (size_t)b_ * 262144 +                    \
                             ((stage) * 4) * 512 + h_ * 8;                    \
            _Pragma("unroll")                                                 \
            for (int il = 0; il < 4; ++il) {                                  \
                regs[il * 2]     = *reinterpret_cast<const float4*>(p);       \
                regs[il * 2 + 1] = *reinterpret_cast<const float4*>(p + 4);   \
                p += 512;                                                     \
            }                                                                 \
        }

    #define X_STS(regs, stage, buf)                                           \
        {                                                                     \
            char* dst = sm + ((buf) ? S_X1 : S_X0);                           \
            _Pragma("unroll")                                                 \
            for (int il = 0; il < 4; ++il) {                                  \
                int kc = il * 16 + h_ * 8;                                    \
                cvt_store<128>(dst, b_, kc,     regs[il * 2]);                \
                cvt_store<128>(dst, b_, kc + 4, regs[il * 2 + 1]);            \
            }                                                                 \
        }

    // ---- compute lane addressing: 8 warps as 4(m) x 2(n), m32 x n32 ----
    const int wid = tid >> 5;
    const int lid = tid & 31;
    const int wm  = (wid & 3) << 5;     // 0/32/64/96
    const int wn  = (wid >> 2) << 5;    // 0/32

    const int ar0 = wm + (lid & 15);
    const int ar1 = ar0 + 16;
    const uint32_t a0_base = ar0 * 128;
    const uint32_t a1_base = ar1 * 128;
    const uint32_t a0_sw   = (uint32_t)(ar0 & 7) << 4;
    const uint32_t a1_sw   = (uint32_t)(ar1 & 7) << 4;
    const uint32_t a_coff  = (uint32_t)(lid >> 4) << 4;  // 0 / 16

    const int bn0 = wn + ((lid >> 4) << 3) + (lid & 7);
    const int bn1 = bn0 + 16;
    const uint32_t b0_base = sb + S_W + bn0 * 512;
    const uint32_t b1_base = sb + S_W + bn1 * 512;
    const uint32_t b0_sw   = (uint32_t)(bn0 & 7) << 4;
    const uint32_t b1_sw   = (uint32_t)(bn1 & 7) << 4;
    const uint32_t b_coff  = (uint32_t)((lid >> 3) & 1) << 4;  // 0 / 16

    float acc[2][4][4];
    #pragma unroll
    for (int i = 0; i < 2; ++i)
        #pragma unroll
        for (int j = 0; j < 4; ++j)
            #pragma unroll
            for (int e = 0; e < 4; ++e) acc[i][j][e] = 0.f;

    // ---- stage 0 load ----
    float4 xr[8];
    X_LDG(xr, 0);
    X_STS(xr, 0, 0);
    __syncthreads();

    // ---- pipelined mainloop over 4 stages ----
    #pragma unroll
    for (int s = 0; s < 4; ++s) {
        if (s < 3) X_LDG(xr, s + 1);        // overlap LDG with compute

        const uint32_t xb = sb + ((s & 1) ? S_X1 : S_X0);
        #pragma unroll
        for (int sl = 0; sl < 4; ++sl) {
            const uint32_t colA = ((uint32_t)sl << 5) | a_coff;
            uint32_t x00, x01, x02, x03, x10, x11, x12, x13;
            ldmatrix_x4(x00, x01, x02, x03, xb + a0_base + (colA ^ a0_sw));
            ldmatrix_x4(x10, x11, x12, x13, xb + a1_base + (colA ^ a1_sw));

            const uint32_t colB = ((uint32_t)(s * 4 + sl) << 5) | b_coff;
            uint32_t u0, u1, u2, u3, v0, v1, v2, v3;
            ldmatrix_x4(u0, u1, u2, u3, b0_base + (colB ^ b0_sw));
            ldmatrix_x4(v0, v1, v2, v3, b1_base + (colB ^ b1_sw));

            mma16816(acc[0][0], x00, x01, x02, x03, u0, u1);
            mma16816(acc[0][1], x00, x01, x02, x03, u2, u3);
            mma16816(acc[0][2], x00, x01, x02, x03, v0, v1);
            mma16816(acc[0][3], x00, x01, x02, x03, v2, v3);
            mma16816(acc[1][0], x10, x11, x12, x13, u0, u1);
            mma16816(acc[1][1], x10, x11, x12, x13, u2, u3);
            mma16816(acc[1][2], x10, x11, x12, x13, v0, v1);
            mma16816(acc[1][3], x10, x11, x12, x13, v2, v3);
        }

        if (s < 3) {
            X_STS(xr, s + 1, (s + 1) & 1);
            __syncthreads();
        }
    }

    // ---- epilogue: bias + relu, scatter ----
    const int g = lid >> 2;
    const int t = lid & 3;
    const float* Bs = reinterpret_cast<const float*>(sm + S_BIAS);
    #pragma unroll
    for (int mt = 0; mt < 2; ++mt) {
        #pragma unroll
        for (int nt = 0; nt < 4; ++nt) {
            int ob  = wn + nt * 8;          // multiple of 8
            int oi  = ob >> 3;
            int oj  = 2 * t;
            float bi0 = Bs[ob + oj];
            float bi1 = Bs[ob + oj + 1];

            size_t colofs = (size_t)(ch * 8 + oi) * 256 + cw * 8 + oj;
            int bg0 = btile * BT + wm + mt * 16 + g;
            float2 w0 = make_float2(fmaxf(acc[mt][nt][0] + bi0, 0.f),
                                    fmaxf(acc[mt][nt][1] + bi1, 0.f));
            *reinterpret_cast<float2*>(out + (size_t)bg0 * 65536 + colofs) = w0;

            int bg1 = bg0 + 8;
            float2 w1 = make_float2(fmaxf(acc[mt][nt][2] + bi0, 0.f),
                                    fmaxf(acc[mt][nt][3] + bi1, 0.f));
            *reinterpret_cast<float2*>(out + (size_t)bg1 * 65536 + colofs) = w1;
        }
    }
}

extern "C" void kernel_launch(void* const* d_in, const int* in_sizes, int n_in,
                              void* d_out, int out_size) {
    const float* x  = (const float*)d_in[0];   // [256,512,512]
    const float* Wk = (const float*)d_in[1];   // [1024,64,256]
    const float* bk = (const float*)d_in[2];   // [1024,64]
    float* out = (float*)d_out;                // [256, 65536]

    cudaFuncSetAttribute(compression_mma_kernel,
                         cudaFuncAttributeMaxDynamicSharedMemorySize, S_TOTAL);

    dim3 grid(2, 1024);   // btile fastest: CTAs sharing W[n] adjacent in wave
    compression_mma_kernel<<<grid, NTHREADS, S_TOTAL>>>(x, Wk, bk, out);
}

// round 9
// speedup vs baseline: 2.7206x; 1.0780x over previous
#include <cuda_runtime.h>
#include <cuda_fp16.h>
#include <cstdint>

// CompressionLayer grouped GEMM via mma.sync fp16 (f32 accumulate).
// y[b,n,o] = relu( sum_k x[b,n,k] * Wk[n,o,k] + bk[n,o] )
// One CTA per chunk n: D[256,64] = X[256,256]*W[64,256]^T processed as two
// 128-batch halves sharing one W load. X pipelined in 8 k-stages of 64
// (double buffer), LDG laid out so 4 lanes cover one full 64B chunk row
// (wavefront-optimal). W converted to fp16 smem once.

#define NTHREADS 256
#define BT 128

// smem layout
#define S_W     0        // 64 rows x 512B (256 fp16), swizzled
#define S_X0    32768    // stage buf 0: 128 rows x 128B (64 fp16)
#define S_X1    49152    // stage buf 1
#define S_BIAS  65536    // 64 f32
#define S_TOTAL 65792

static __device__ __forceinline__ uint32_t smem_u32(const void* p) {
    uint32_t a;
    asm("{ .reg .u64 t; cvta.to.shared.u64 t, %1; cvt.u32.u64 %0, t; }"
        : "=r"(a) : "l"(p));
    return a;
}

static __device__ __forceinline__ void ldmatrix_x4(uint32_t& a0, uint32_t& a1,
                                                   uint32_t& a2, uint32_t& a3,
                                                   uint32_t addr) {
    asm volatile("ldmatrix.sync.aligned.m8n8.x4.shared.b16 {%0,%1,%2,%3}, [%4];"
                 : "=r"(a0), "=r"(a1), "=r"(a2), "=r"(a3) : "r"(addr));
}

static __device__ __forceinline__ void mma16816(float* c, uint32_t a0, uint32_t a1,
                                                uint32_t a2, uint32_t a3,
                                                uint32_t b0, uint32_t b1) {
    asm volatile(
        "mma.sync.aligned.m16n8k16.row.col.f32.f16.f16.f32 "
        "{%0,%1,%2,%3}, {%4,%5,%6,%7}, {%8,%9}, {%0,%1,%2,%3};"
        : "+f"(c[0]), "+f"(c[1]), "+f"(c[2]), "+f"(c[3])
        : "r"(a0), "r"(a1), "r"(a2), "r"(a3), "r"(b0), "r"(b1));
}

// f32x4 -> fp16x4, 8B store into swizzled row of given byte stride
template <int STRIDE>
static __device__ __forceinline__ void cvt_store(char* dst, int row, int kcol,
                                                 float4 v) {
    __half2 h01 = __floats2half2_rn(v.x, v.y);
    __half2 h23 = __floats2half2_rn(v.z, v.w);
    int phys = row * STRIDE + ((kcol * 2) ^ ((row & 7) << 4));
    *reinterpret_cast<uint2*>(dst + phys) =
        make_uint2(*(uint32_t*)&h01, *(uint32_t*)&h23);
}

__global__ void __launch_bounds__(NTHREADS, 2)
compression_mma_kernel(const float* __restrict__ xg,
                       const float* __restrict__ Wg,
                       const float* __restrict__ bkg,
                       float* __restrict__ out) {
    extern __shared__ char sm[];
    const uint32_t sb = smem_u32(sm);
    const int tid = threadIdx.x;
    const int wid = tid >> 5;
    const int lid = tid & 31;

    const int n  = blockIdx.x;      // 0..1023
    const int ch = n >> 5;
    const int cw = n & 31;

    // ---- prologue: W[n] 64x256 f32 -> fp16 smem (once), bias ----
    {
        const float4* Wg4 = reinterpret_cast<const float4*>(Wg + (size_t)n * 64 * 256);
        #pragma unroll
        for (int it = 0; it < 16; ++it) {
            int e  = tid + it * NTHREADS;   // 0..4095
            int o  = e >> 6;
            int k4 = (e & 63) << 2;
            cvt_store<512>(sm + S_W, o, k4, Wg4[e]);
        }
    }
    if (tid < 64)
        reinterpret_cast<float*>(sm + S_BIAS)[tid] = bkg[n * 64 + tid];

    // ---- X loader lane mapping: 4 lanes cover one full 64B chunk row ----
    // instr il: (batch = w*16 + il*2 + (lid>>4), row i = (lid>>2)&3, quad lid&3)
    const float* xbase = xg + (size_t)(ch * 16) * 512 + cw * 16;
    const int ld_b = wid * 16 + (lid >> 4);      // base batch (within 128-tile)
    const int ld_i = (lid >> 2) & 3;             // row within stage's 4 rows
    const int ld_j = (lid & 3) << 2;             // float offset in row
    const int sts_k = ld_i * 16 + ld_j;          // fp16 col for STS

    #define X_LDG(regs, bt, s)                                                \
        {                                                                     \
            const float* p0 = xbase +                                         \
                (size_t)((bt) * BT + ld_b) * 262144 +                         \
                ((s) * 4 + ld_i) * 512 + ld_j;                                \
            _Pragma("unroll")                                                 \
            for (int il = 0; il < 8; ++il)                                    \
                regs[il] = *reinterpret_cast<const float4*>(                  \
                    p0 + (size_t)il * 2 * 262144);                            \
        }

    #define X_STS(regs, buf)                                                  \
        {                                                                     \
            char* dst = sm + ((buf) ? S_X1 : S_X0);                           \
            _Pragma("unroll")                                                 \
            for (int il = 0; il < 8; ++il)                                    \
                cvt_store<128>(dst, ld_b + il * 2, sts_k, regs[il]);          \
        }

    // ---- compute lane addressing: 8 warps as 4(m) x 2(n), m32 x n32 ----
    const int wm  = (wid & 3) << 5;     // 0/32/64/96
    const int wn  = (wid >> 2) << 5;    // 0/32

    const int ar0 = wm + (lid & 15);
    const int ar1 = ar0 + 16;
    const uint32_t a0_base = ar0 * 128;
    const uint32_t a1_base = ar1 * 128;
    const uint32_t a0_sw   = (uint32_t)(ar0 & 7) << 4;
    const uint32_t a1_sw   = (uint32_t)(ar1 & 7) << 4;
    const uint32_t a_coff  = (uint32_t)(lid >> 4) << 4;  // 0 / 16

    const int bn0 = wn + ((lid >> 4) << 3) + (lid & 7);
    const int bn1 = bn0 + 16;
    const uint32_t b0_base = sb + S_W + bn0 * 512;
    const uint32_t b1_base = sb + S_W + bn1 * 512;
    const uint32_t b0_sw   = (uint32_t)(bn0 & 7) << 4;
    const uint32_t b1_sw   = (uint32_t)(bn1 & 7) << 4;
    const uint32_t b_coff  = (uint32_t)((lid >> 3) & 1) << 4;  // 0 / 16

    float acc[2][4][4];
    #pragma unroll
    for (int i = 0; i < 2; ++i)
        #pragma unroll
        for (int j = 0; j < 4; ++j)
            #pragma unroll
            for (int e = 0; e < 4; ++e) acc[i][j][e] = 0.f;

    // one k-quarter (16 of K) of MMAs from stage buffer xb
    auto compute_stage = [&](uint32_t xb, int kq) {
        #pragma unroll
        for (int sl = 0; sl < 4; ++sl) {
            const uint32_t colA = ((uint32_t)sl << 5) | a_coff;
            uint32_t x00, x01, x02, x03, x10, x11, x12, x13;
            ldmatrix_x4(x00, x01, x02, x03, xb + a0_base + (colA ^ a0_sw));
            ldmatrix_x4(x10, x11, x12, x13, xb + a1_base + (colA ^ a1_sw));

            const uint32_t colB = ((uint32_t)(kq * 4 + sl) << 5) | b_coff;
            uint32_t u0, u1, u2, u3, v0, v1, v2, v3;
            ldmatrix_x4(u0, u1, u2, u3, b0_base + (colB ^ b0_sw));
            ldmatrix_x4(v0, v1, v2, v3, b1_base + (colB ^ b1_sw));

            mma16816(acc[0][0], x00, x01, x02, x03, u0, u1);
            mma16816(acc[0][1], x00, x01, x02, x03, u2, u3);
            mma16816(acc[0][2], x00, x01, x02, x03, v0, v1);
            mma16816(acc[0][3], x00, x01, x02, x03, v2, v3);
            mma16816(acc[1][0], x10, x11, x12, x13, u0, u1);
            mma16816(acc[1][1], x10, x11, x12, x13, u2, u3);
            mma16816(acc[1][2], x10, x11, x12, x13, v0, v1);
            mma16816(acc[1][3], x10, x11, x12, x13, v2, v3);
        }
    };

    const int g = lid >> 2;
    const int t = lid & 3;
    auto epilogue = [&](int bt) {
        const float* Bs = reinterpret_cast<const float*>(sm + S_BIAS);
        #pragma unroll
        for (int mt = 0; mt < 2; ++mt) {
            #pragma unroll
            for (int nt = 0; nt < 4; ++nt) {
                int ob  = wn + nt * 8;
                int oi  = ob >> 3;
                int oj  = 2 * t;
                float bi0 = Bs[ob + oj];
                float bi1 = Bs[ob + oj + 1];

                size_t colofs = (size_t)(ch * 8 + oi) * 256 + cw * 8 + oj;
                int bg0 = bt * BT + wm + mt * 16 + g;
                float2 w0 = make_float2(fmaxf(acc[mt][nt][0] + bi0, 0.f),
                                        fmaxf(acc[mt][nt][1] + bi1, 0.f));
                *reinterpret_cast<float2*>(out + (size_t)bg0 * 65536 + colofs) = w0;

                int bg1 = bg0 + 8;
                float2 w1 = make_float2(fmaxf(acc[mt][nt][2] + bi0, 0.f),
                                        fmaxf(acc[mt][nt][3] + bi1, 0.f));
                *reinterpret_cast<float2*>(out + (size_t)bg1 * 65536 + colofs) = w1;
            }
        }
    };

    // ---- 8-stage continuous pipeline across both batch halves ----
    float4 xr[8];
    X_LDG(xr, 0, 0);
    X_STS(xr, 0);
    __syncthreads();

    #pragma unroll
    for (int ls = 0; ls < 8; ++ls) {
        if (ls < 7) X_LDG(xr, (ls + 1) >> 2, (ls + 1) & 3);

        compute_stage(sb + ((ls & 1) ? S_X1 : S_X0), ls & 3);

        if (ls < 7) {
            X_STS(xr, (ls + 1) & 1);
            __syncthreads();
        }

        if (ls == 3) {
            epilogue(0);          // overlaps with bt1 stage-0 already loaded
            #pragma unroll
            for (int i = 0; i < 2; ++i)
                #pragma unroll
                for (int j = 0; j < 4; ++j)
                    #pragma unroll
                    for (int e = 0; e < 4; ++e) acc[i][j][e] = 0.f;
        }
    }
    epilogue(1);

    #undef X_LDG
    #undef X_STS
}

extern "C" void kernel_launch(void* const* d_in, const int* in_sizes, int n_in,
                              void* d_out, int out_size) {
    const float* x  = (const float*)d_in[0];   // [256,512,512]
    const float* Wk = (const float*)d_in[1];   // [1024,64,256]
    const float* bk = (const float*)d_in[2];   // [1024,64]
    float* out = (float*)d_out;                // [256, 65536]

    cudaFuncSetAttribute(compression_mma_kernel,
                         cudaFuncAttributeMaxDynamicSharedMemorySize, S_TOTAL);

    compression_mma_kernel<<<1024, NTHREADS, S_TOTAL>>>(x, Wk, bk, out);
}

// round 10
// speedup vs baseline: 2.8707x; 1.0552x over previous
#include <cuda_runtime.h>
#include <cuda_fp16.h>
#include <cstdint>

// CompressionLayer grouped GEMM via mma.sync fp16 (f32 accumulate).
// y[b,n,o] = relu( sum_k x[b,n,k] * Wk[n,o,k] + bk[n,o] )
// One CTA per chunk n: D[256,64] = X[256,256]*W[64,256]^T as two 128-batch
// halves sharing one W load. X pipelined in 16 k-stages of 32 with TWO-stage
// latency cover: iter s issues LDG(s+2), computes stage s, stores stage s+1
// from last iter's registers. Stage bufs are 128B-row padded for swizzle.

#define NTHREADS 256
#define BT 128

// smem layout
#define S_W     0        // 64 rows x 512B (256 fp16), swizzled
#define S_X0    32768    // stage buf 0: 128 rows x 128B (k=32 fp16 + pad)
#define S_X1    49152    // stage buf 1
#define S_BIAS  65536    // 64 f32
#define S_TOTAL 65792

static __device__ __forceinline__ uint32_t smem_u32(const void* p) {
    uint32_t a;
    asm("{ .reg .u64 t; cvta.to.shared.u64 t, %1; cvt.u32.u64 %0, t; }"
        : "=r"(a) : "l"(p));
    return a;
}

static __device__ __forceinline__ void ldmatrix_x4(uint32_t& a0, uint32_t& a1,
                                                   uint32_t& a2, uint32_t& a3,
                                                   uint32_t addr) {
    asm volatile("ldmatrix.sync.aligned.m8n8.x4.shared.b16 {%0,%1,%2,%3}, [%4];"
                 : "=r"(a0), "=r"(a1), "=r"(a2), "=r"(a3) : "r"(addr));
}

static __device__ __forceinline__ void mma16816(float* c, uint32_t a0, uint32_t a1,
                                                uint32_t a2, uint32_t a3,
                                                uint32_t b0, uint32_t b1) {
    asm volatile(
        "mma.sync.aligned.m16n8k16.row.col.f32.f16.f16.f32 "
        "{%0,%1,%2,%3}, {%4,%5,%6,%7}, {%8,%9}, {%0,%1,%2,%3};"
        : "+f"(c[0]), "+f"(c[1]), "+f"(c[2]), "+f"(c[3])
        : "r"(a0), "r"(a1), "r"(a2), "r"(a3), "r"(b0), "r"(b1));
}

// f32x4 -> fp16x4, 8B store into swizzled row of given byte stride
template <int STRIDE>
static __device__ __forceinline__ void cvt_store(char* dst, int row, int kcol,
                                                 float4 v) {
    __half2 h01 = __floats2half2_rn(v.x, v.y);
    __half2 h23 = __floats2half2_rn(v.z, v.w);
    int phys = row * STRIDE + ((kcol * 2) ^ ((row & 7) << 4));
    *reinterpret_cast<uint2*>(dst + phys) =
        make_uint2(*(uint32_t*)&h01, *(uint32_t*)&h23);
}

__global__ void __launch_bounds__(NTHREADS, 2)
compression_mma_kernel(const float* __restrict__ xg,
                       const float* __restrict__ Wg,
                       const float* __restrict__ bkg,
                       float* __restrict__ out) {
    extern __shared__ char sm[];
    const uint32_t sb = smem_u32(sm);
    const int tid = threadIdx.x;
    const int wid = tid >> 5;
    const int lid = tid & 31;

    const int n  = blockIdx.x;      // 0..1023
    const int ch = n >> 5;
    const int cw = n & 31;

    // ---- prologue: W[n] 64x256 f32 -> fp16 smem (once), bias ----
    {
        const float4* Wg4 = reinterpret_cast<const float4*>(Wg + (size_t)n * 64 * 256);
        #pragma unroll
        for (int it = 0; it < 16; ++it) {
            int e  = tid + it * NTHREADS;   // 0..4095
            int o  = e >> 6;
            int k4 = (e & 63) << 2;
            cvt_store<512>(sm + S_W, o, k4, Wg4[e]);
        }
    }
    if (tid < 64)
        reinterpret_cast<float*>(sm + S_BIAS)[tid] = bkg[n * 64 + tid];

    // ---- X loader lane mapping: 4 lanes cover one full 64B chunk row ----
    // stage st (0..15): bt = st>>3, s8 = st&7 covers chunk rows 2*s8, 2*s8+1.
    // per thread 4 LDG.128: il -> batch = il*32 + wid*4 + (lid>>3),
    //                       ri = (lid>>2)&1, quad = lid&3.
    const float* xbase = xg + (size_t)(ch * 16) * 512 + cw * 16;
    const int ld_b  = wid * 4 + (lid >> 3);      // base batch (of 32-group)
    const int ld_ri = (lid >> 2) & 1;            // row within stage's 2 rows
    const int ld_j  = (lid & 3) << 2;            // float offset in row
    const int sts_k = ld_ri * 16 + ld_j;         // fp16 col for STS

    #define X_LDG(regs, st)                                                   \
        {                                                                     \
            const float* p0 = xbase +                                         \
                (size_t)(((st) >> 3) * BT + ld_b) * 262144 +                  \
                (((st) & 7) * 2 + ld_ri) * 512 + ld_j;                        \
            _Pragma("unroll")                                                 \
            for (int il = 0; il < 4; ++il)                                    \
                regs[il] = *reinterpret_cast<const float4*>(                  \
                    p0 + (size_t)il * 32 * 262144);                           \
        }

    #define X_STS(regs, buf)                                                  \
        {                                                                     \
            char* dst = sm + ((buf) ? S_X1 : S_X0);                           \
            _Pragma("unroll")                                                 \
            for (int il = 0; il < 4; ++il)                                    \
                cvt_store<128>(dst, ld_b + il * 32, sts_k, regs[il]);         \
        }

    // ---- compute lane addressing: 8 warps as 4(m) x 2(n), m32 x n32 ----
    const int wm  = (wid & 3) << 5;     // 0/32/64/96
    const int wn  = (wid >> 2) << 5;    // 0/32

    const int ar0 = wm + (lid & 15);
    const int ar1 = ar0 + 16;
    const uint32_t a0_base = ar0 * 128;
    const uint32_t a1_base = ar1 * 128;
    const uint32_t a0_sw   = (uint32_t)(ar0 & 7) << 4;
    const uint32_t a1_sw   = (uint32_t)(ar1 & 7) << 4;
    const uint32_t a_coff  = (uint32_t)(lid >> 4) << 4;  // 0 / 16

    const int bn0 = wn + ((lid >> 4) << 3) + (lid & 7);
    const int bn1 = bn0 + 16;
    const uint32_t b0_base = sb + S_W + bn0 * 512;
    const uint32_t b1_base = sb + S_W + bn1 * 512;
    const uint32_t b0_sw   = (uint32_t)(bn0 & 7) << 4;
    const uint32_t b1_sw   = (uint32_t)(bn1 & 7) << 4;
    const uint32_t b_coff  = (uint32_t)((lid >> 3) & 1) << 4;  // 0 / 16

    float acc[2][4][4];
    #pragma unroll
    for (int i = 0; i < 2; ++i)
        #pragma unroll
        for (int j = 0; j < 4; ++j)
            #pragma unroll
            for (int e = 0; e < 4; ++e) acc[i][j][e] = 0.f;

    // one k=32 stage of MMAs from stage buffer xb; s8 = chunk-row-pair index
    auto compute_stage = [&](uint32_t xb, int s8) {
        #pragma unroll
        for (int sl = 0; sl < 2; ++sl) {
            const uint32_t colA = ((uint32_t)sl << 5) | a_coff;
            uint32_t x00, x01, x02, x03, x10, x11, x12, x13;
            ldmatrix_x4(x00, x01, x02, x03, xb + a0_base + (colA ^ a0_sw));
            ldmatrix_x4(x10, x11, x12, x13, xb + a1_base + (colA ^ a1_sw));

            const uint32_t colB = ((uint32_t)(s8 * 2 + sl) << 5) | b_coff;
            uint32_t u0, u1, u2, u3, v0, v1, v2, v3;
            ldmatrix_x4(u0, u1, u2, u3, b0_base + (colB ^ b0_sw));
            ldmatrix_x4(v0, v1, v2, v3, b1_base + (colB ^ b1_sw));

            mma16816(acc[0][0], x00, x01, x02, x03, u0, u1);
            mma16816(acc[0][1], x00, x01, x02, x03, u2, u3);
            mma16816(acc[0][2], x00, x01, x02, x03, v0, v1);
            mma16816(acc[0][3], x00, x01, x02, x03, v2, v3);
            mma16816(acc[1][0], x10, x11, x12, x13, u0, u1);
            mma16816(acc[1][1], x10, x11, x12, x13, u2, u3);
            mma16816(acc[1][2], x10, x11, x12, x13, v0, v1);
            mma16816(acc[1][3], x10, x11, x12, x13, v2, v3);
        }
    };

    const int g = lid >> 2;
    const int t = lid & 3;
    auto epilogue = [&](int bt) {
        const float* Bs = reinterpret_cast<const float*>(sm + S_BIAS);
        #pragma unroll
        for (int mt = 0; mt < 2; ++mt) {
            #pragma unroll
            for (int nt = 0; nt < 4; ++nt) {
                int ob  = wn + nt * 8;
                int oi  = ob >> 3;
                int oj  = 2 * t;
                float bi0 = Bs[ob + oj];
                float bi1 = Bs[ob + oj + 1];

                size_t colofs = (size_t)(ch * 8 + oi) * 256 + cw * 8 + oj;
                int bg0 = bt * BT + wm + mt * 16 + g;
                float2 w0 = make_float2(fmaxf(acc[mt][nt][0] + bi0, 0.f),
                                        fmaxf(acc[mt][nt][1] + bi1, 0.f));
                *reinterpret_cast<float2*>(out + (size_t)bg0 * 65536 + colofs) = w0;

                int bg1 = bg0 + 8;
                float2 w1 = make_float2(fmaxf(acc[mt][nt][2] + bi0, 0.f),
                                        fmaxf(acc[mt][nt][3] + bi1, 0.f));
                *reinterpret_cast<float2*>(out + (size_t)bg1 * 65536 + colofs) = w1;
            }
        }
    };

    // ---- 16-stage pipeline, two-stage LDG latency cover ----
    // reg set for stage st is r[st & 1]; buffer for stage st is buf[st & 1].
    float4 r0[4], r1[4];
    X_LDG(r0, 0);
    X_STS(r0, 0);
    X_LDG(r1, 1);
    __syncthreads();

    #pragma unroll
    for (int st = 0; st < 16; ++st) {
        if (st < 14) {
            if (st & 1) { X_LDG(r1, st + 2); }
            else        { X_LDG(r0, st + 2); }
        }

        compute_stage(sb + ((st & 1) ? S_X1 : S_X0), st & 7);

        if (st < 15) {
            if ((st + 1) & 1) { X_STS(r1, 1); }
            else              { X_STS(r0, 0); }
            __syncthreads();
        }

        if (st == 7) {
            epilogue(0);
            #pragma unroll
            for (int i = 0; i < 2; ++i)
                #pragma unroll
                for (int j = 0; j < 4; ++j)
                    #pragma unroll
                    for (int e = 0; e < 4; ++e) acc[i][j][e] = 0.f;
        }
    }
    epilogue(1);

    #undef X_LDG
    #undef X_STS
}

extern "C" void kernel_launch(void* const* d_in, const int* in_sizes, int n_in,
                              void* d_out, int out_size) {
    const float* x  = (const float*)d_in[0];   // [256,512,512]
    const float* Wk = (const float*)d_in[1];   // [1024,64,256]
    const float* bk = (const float*)d_in[2];   // [1024,64]
    float* out = (float*)d_out;                // [256, 65536]

    cudaFuncSetAttribute(compression_mma_kernel,
                         cudaFuncAttributeMaxDynamicSharedMemorySize, S_TOTAL);

    compression_mma_kernel<<<1024, NTHREADS, S_TOTAL>>>(x, Wk, bk, out);
}